// round 1
// baseline (speedup 1.0000x reference)
#include <cuda_runtime.h>

// Problem constants (fixed by the reference).
#define BB 32768
#define FF 128
#define HH 64
#define THREADS 128
#define ROWS_PER_BLOCK 128
#define NPART 4
#define F_PER_PART (FF / NPART)

// Scratch for per-partition partial logits (no cudaMalloc allowed).
__device__ float g_partial[NPART * BB];

// ---- packed fp32x2 helpers (Blackwell FFMA2) ----
__device__ __forceinline__ unsigned long long fma2(unsigned long long a,
                                                   unsigned long long b,
                                                   unsigned long long c) {
    unsigned long long d;
    asm("fma.rn.f32x2 %0, %1, %2, %3;" : "=l"(d) : "l"(a), "l"(b), "l"(c));
    return d;
}
__device__ __forceinline__ unsigned long long pack2(float lo, float hi) {
    unsigned long long r;
    asm("mov.b64 %0, {%1, %2};" : "=l"(r) : "f"(lo), "f"(hi));
    return r;
}
__device__ __forceinline__ void unpack2(unsigned long long v, float& lo, float& hi) {
    asm("mov.b64 {%0, %1}, %2;" : "=f"(lo), "=f"(hi) : "l"(v));
}

// w2 staged transposed: w2s[g][h], row stride 68 floats (272B: 16B-aligned rows,
// conflict-spread staging writes). Inner-loop reads are warp-broadcast (same
// address across the warp), so read conflicts are irrelevant.
#define W2S_STRIDE 68

__global__ __launch_bounds__(THREADS)
void mlp_contrib_kernel(const float* __restrict__ x,
                        const float* __restrict__ w1,
                        const float* __restrict__ b1,
                        const float* __restrict__ w2,
                        const float* __restrict__ b2,
                        const float* __restrict__ w3,
                        const float* __restrict__ b3) {
    __shared__ __align__(16) float w2s[HH * W2S_STRIDE];
    __shared__ float w1s[HH], b1s[HH], b2s[HH], w3s[HH];

    const int tid = threadIdx.x;
    const int b = blockIdx.x * ROWS_PER_BLOCK + tid;
    const int part = blockIdx.y;
    const int f_begin = part * F_PER_PART;

    float logit = 0.0f;

    for (int f = f_begin; f < f_begin + F_PER_PART; ++f) {
        __syncthreads();  // previous iteration done reading shared

        // ---- stage weights for feature f ----
        const float4* W24 = reinterpret_cast<const float4*>(w2 + (size_t)f * (HH * HH));
        #pragma unroll
        for (int i = 0; i < 8; ++i) {
            int idx = tid + i * THREADS;        // float4 index, 0..1023
            float4 v = W24[idx];
            int h = idx >> 4;                   // (idx*4)/64
            int g = (idx << 2) & 63;            // (idx*4)%64
            w2s[(g + 0) * W2S_STRIDE + h] = v.x;
            w2s[(g + 1) * W2S_STRIDE + h] = v.y;
            w2s[(g + 2) * W2S_STRIDE + h] = v.z;
            w2s[(g + 3) * W2S_STRIDE + h] = v.w;
        }
        if (tid < HH) {
            w1s[tid] = w1[f * HH + tid];
            b1s[tid] = b1[f * HH + tid];
            b2s[tid] = b2[f * HH + tid];
            w3s[tid] = w3[f * HH + tid];
        }
        __syncthreads();

        const float xv = __ldg(x + (size_t)b * FF + f);

        // ---- layer 1: h1 = relu(x*w1 + b1), packed into 32 x f32x2 ----
        unsigned long long h1p[HH / 2];
        #pragma unroll
        for (int hp = 0; hp < HH / 2; ++hp) {
            float a0 = fmaxf(fmaf(xv, w1s[2 * hp], b1s[2 * hp]), 0.0f);
            float a1 = fmaxf(fmaf(xv, w1s[2 * hp + 1], b1s[2 * hp + 1]), 0.0f);
            h1p[hp] = pack2(a0, a1);
        }

        // ---- layer 2 + layer 3 fused: contrib = sum_g relu(h1.w2[:,g]+b2)*w3 + b3 ----
        float fc = __ldg(b3 + f);
        #pragma unroll 4
        for (int g = 0; g < HH; g += 2) {
            const ulonglong2* r0 =
                reinterpret_cast<const ulonglong2*>(w2s + g * W2S_STRIDE);
            const ulonglong2* r1 =
                reinterpret_cast<const ulonglong2*>(w2s + (g + 1) * W2S_STRIDE);
            unsigned long long acc0 = 0ull, acc1 = 0ull;
            #pragma unroll
            for (int q = 0; q < 16; ++q) {
                ulonglong2 u = r0[q];
                ulonglong2 v = r1[q];
                acc0 = fma2(h1p[2 * q],     u.x, acc0);
                acc0 = fma2(h1p[2 * q + 1], u.y, acc0);
                acc1 = fma2(h1p[2 * q],     v.x, acc1);
                acc1 = fma2(h1p[2 * q + 1], v.y, acc1);
            }
            float s0lo, s0hi, s1lo, s1hi;
            unpack2(acc0, s0lo, s0hi);
            unpack2(acc1, s1lo, s1hi);
            float h2a = fmaxf((s0lo + s0hi) + b2s[g],     0.0f);
            float h2b = fmaxf((s1lo + s1hi) + b2s[g + 1], 0.0f);
            fc = fmaf(h2a, w3s[g],     fc);
            fc = fmaf(h2b, w3s[g + 1], fc);
        }
        logit += fc;
    }

    g_partial[part * BB + b] = logit;
}

__global__ void finalize_kernel(const float* __restrict__ bias,
                                float* __restrict__ out) {
    int b = blockIdx.x * blockDim.x + threadIdx.x;
    if (b >= BB) return;
    float l = (g_partial[b] + g_partial[BB + b]) +
              (g_partial[2 * BB + b] + g_partial[3 * BB + b]) + bias[0];
    float p = 1.0f / (1.0f + expf(-l));
    out[2 * b + 0] = 1.0f - p;
    out[2 * b + 1] = p;
}

extern "C" void kernel_launch(void* const* d_in, const int* in_sizes, int n_in,
                              void* d_out, int out_size) {
    const float* x    = (const float*)d_in[0];
    const float* w1   = (const float*)d_in[1];
    const float* b1   = (const float*)d_in[2];
    const float* w2   = (const float*)d_in[3];
    const float* b2   = (const float*)d_in[4];
    const float* w3   = (const float*)d_in[5];
    const float* b3   = (const float*)d_in[6];
    const float* bias = (const float*)d_in[7];
    float* out = (float*)d_out;

    dim3 grid(BB / ROWS_PER_BLOCK, NPART);   // 256 x 4 = 1024 CTAs
    mlp_contrib_kernel<<<grid, THREADS>>>(x, w1, b1, w2, b2, w3, b3);
    finalize_kernel<<<BB / 256, 256>>>(bias, out);
}

// round 3
// speedup vs baseline: 2.8384x; 2.8384x over previous
#include <cuda_runtime.h>
#include <cuda_bf16.h>
#include <cstdint>

#define BB 32768
#define FF 128
#define HH 64
#define THREADS 256
#define WARPS 8
#define ROWS_PER_CTA 1024
#define NCHUNK (BB / ROWS_PER_CTA)   // 32
#define STEPS (ROWS_PER_CTA / 16)    // 64
#define H1S 72                        // padded h1 row stride (bf16 elems) -> conflict-free

// ---- device scratch (no cudaMalloc allowed) ----
__device__ __align__(16) uint32_t g_bfragH[FF * 2048];   // per-lane packed B frags (hi)
__device__ __align__(16) uint32_t g_bfragL[FF * 2048];   // (lo)
__device__ float g_contrib[FF * BB];                     // per-(feature,row) contribution

// pack two fp32 -> bf16x2 (lo = v0, hi = v1)
__device__ __forceinline__ uint32_t pack_bf16(float v0, float v1) {
    uint32_t r;
    asm("cvt.rn.bf16x2.f32 %0, %1, %2;" : "=r"(r) : "f"(v1), "f"(v0));
    return r;
}

__device__ __forceinline__ void mma16816(float& d0, float& d1, float& d2, float& d3,
                                         uint32_t a0, uint32_t a1, uint32_t a2, uint32_t a3,
                                         uint32_t b0, uint32_t b1) {
    asm volatile(
        "mma.sync.aligned.m16n8k16.row.col.f32.bf16.bf16.f32 "
        "{%0,%1,%2,%3}, {%4,%5,%6,%7}, {%8,%9}, {%0,%1,%2,%3};"
        : "+f"(d0), "+f"(d1), "+f"(d2), "+f"(d3)
        : "r"(a0), "r"(a1), "r"(a2), "r"(a3), "r"(b0), "r"(b1));
}

// -------- prep: split w2 into bf16 hi/lo packed in m16n8k16 B-fragment order --------
// frag element mapping (PTX m16n8k16 B, k16 x n8):
//   b_i (i=0,1): k = q*16 + (lane%4)*2 + {0,1} + 8*i,  n = lane/4
__global__ void prep_kernel(const float* __restrict__ w2) {
    int e = blockIdx.x * blockDim.x + threadIdx.x;   // < FF*2048
    int lane = e & 31;
    int i = (e >> 5) & 1;
    int q = (e >> 6) & 3;
    int w = (e >> 8) & 7;
    int f = e >> 11;
    int k0 = q * 16 + (lane & 3) * 2 + 8 * i;
    int g = w * 8 + (lane >> 2);
    float v0 = w2[f * 4096 + k0 * 64 + g];         // w2[f][k0][g]
    float v1 = w2[f * 4096 + (k0 + 1) * 64 + g];
    uint32_t hi = pack_bf16(v0, v1);
    float r0 = v0 - __uint_as_float(hi << 16);
    float r1 = v1 - __uint_as_float(hi & 0xFFFF0000u);
    g_bfragH[e] = hi;
    g_bfragL[e] = pack_bf16(r0, r1);
}

// -------- main kernel --------
__global__ __launch_bounds__(THREADS)
void mlp_mma_kernel(const float* __restrict__ x,
                    const float* __restrict__ w1,
                    const float* __restrict__ b1,
                    const float* __restrict__ b2,
                    const float* __restrict__ w3,
                    const float* __restrict__ b3) {
    __shared__ __align__(16) __nv_bfloat16 h1h[16 * H1S];
    __shared__ __align__(16) __nv_bfloat16 h1l[16 * H1S];
    __shared__ float wsum[WARPS][16];
    __shared__ float w1s[HH], b1s[HH], b2s[HH], w3s[HH];

    const int tid = threadIdx.x;
    const int warp = tid >> 5, lane = tid & 31;
    const int f = blockIdx.y;
    const int row0 = blockIdx.x * ROWS_PER_CTA;

    if (tid < HH) {
        w1s[tid] = w1[f * HH + tid];
        b1s[tid] = b1[f * HH + tid];
        b2s[tid] = b2[f * HH + tid];
        w3s[tid] = w3[f * HH + tid];
    }
    const float b3f = __ldg(b3 + f);

    // B fragments held in registers for the whole CTA (warp owns n-slice warp*8..+8)
    uint32_t bh[4][2], bl[4][2];
    {
        int base = f * 2048 + warp * 256 + lane;
        #pragma unroll
        for (int q = 0; q < 4; ++q)
            #pragma unroll
            for (int i = 0; i < 2; ++i) {
                bh[q][i] = g_bfragH[base + q * 64 + i * 32];
                bl[q][i] = g_bfragL[base + q * 64 + i * 32];
            }
    }

    const int m = lane >> 2, c = lane & 3;
    const int hr = tid >> 4;             // h1 row this thread fills
    const int hc = (tid & 15) * 4;       // h1 col base (4 values)
    const int n0 = warp * 8 + 2 * c;

    uint2* h1h_st = reinterpret_cast<uint2*>(h1h + hr * H1S + hc);
    uint2* h1l_st = reinterpret_cast<uint2*>(h1l + hr * H1S + hc);
    const __nv_bfloat16* Ah0 = h1h + m * H1S + 2 * c;
    const __nv_bfloat16* Ah1 = h1h + (m + 8) * H1S + 2 * c;
    const __nv_bfloat16* Al0 = h1l + m * H1S + 2 * c;
    const __nv_bfloat16* Al1 = h1l + (m + 8) * H1S + 2 * c;

    __syncthreads();   // weight smem ready

    for (int stp = 0; stp < STEPS; ++stp) {
        const int rbase = row0 + stp * 16;

        // ---- layer 1 for 16 rows: h1 = relu(x*w1+b1), bf16 hi/lo split ----
        {
            const float xv = __ldg(x + (size_t)(rbase + hr) * FF + f);
            float4 wv = *(const float4*)(w1s + hc);
            float4 bv = *(const float4*)(b1s + hc);
            float v0 = fmaxf(fmaf(xv, wv.x, bv.x), 0.f);
            float v1 = fmaxf(fmaf(xv, wv.y, bv.y), 0.f);
            float v2 = fmaxf(fmaf(xv, wv.z, bv.z), 0.f);
            float v3 = fmaxf(fmaf(xv, wv.w, bv.w), 0.f);
            uint32_t hw0 = pack_bf16(v0, v1);
            uint32_t hw1 = pack_bf16(v2, v3);
            uint32_t lw0 = pack_bf16(v0 - __uint_as_float(hw0 << 16),
                                     v1 - __uint_as_float(hw0 & 0xFFFF0000u));
            uint32_t lw1 = pack_bf16(v2 - __uint_as_float(hw1 << 16),
                                     v3 - __uint_as_float(hw1 & 0xFFFF0000u));
            *h1h_st = make_uint2(hw0, hw1);
            *h1l_st = make_uint2(lw0, lw1);
        }
        __syncthreads();   // (A) h1 visible; prev reduce done

        // ---- grouped GEMM tile: 3-pass bf16-split MMA ----
        float d0 = 0.f, d1 = 0.f, d2 = 0.f, d3 = 0.f;
        #pragma unroll
        for (int q = 0; q < 4; ++q) {
            uint32_t a0 = *(const uint32_t*)(Ah0 + q * 16);
            uint32_t a1 = *(const uint32_t*)(Ah1 + q * 16);
            uint32_t a2 = *(const uint32_t*)(Ah0 + q * 16 + 8);
            uint32_t a3 = *(const uint32_t*)(Ah1 + q * 16 + 8);
            mma16816(d0, d1, d2, d3, a0, a1, a2, a3, bh[q][0], bh[q][1]);
            mma16816(d0, d1, d2, d3, a0, a1, a2, a3, bl[q][0], bl[q][1]);
            uint32_t c0 = *(const uint32_t*)(Al0 + q * 16);
            uint32_t c1 = *(const uint32_t*)(Al1 + q * 16);
            uint32_t c2 = *(const uint32_t*)(Al0 + q * 16 + 8);
            uint32_t c3 = *(const uint32_t*)(Al1 + q * 16 + 8);
            mma16816(d0, d1, d2, d3, c0, c1, c2, c3, bh[q][0], bh[q][1]);
        }

        // ---- epilogue: relu(D + b2) . w3, reduce to per-row contrib ----
        {
            float B0 = b2s[n0], B1 = b2s[n0 + 1];
            float W0 = w3s[n0], W1 = w3s[n0 + 1];
            float e0 = fmaf(fmaxf(d0 + B0, 0.f), W0, fmaxf(d1 + B1, 0.f) * W1);
            float e1 = fmaf(fmaxf(d2 + B0, 0.f), W0, fmaxf(d3 + B1, 0.f) * W1);
            e0 += __shfl_xor_sync(0xFFFFFFFFu, e0, 1);
            e0 += __shfl_xor_sync(0xFFFFFFFFu, e0, 2);
            e1 += __shfl_xor_sync(0xFFFFFFFFu, e1, 1);
            e1 += __shfl_xor_sync(0xFFFFFFFFu, e1, 2);
            if (c == 0) {
                wsum[warp][m] = e0;
                wsum[warp][m + 8] = e1;
            }
        }
        __syncthreads();   // (B) wsum visible; h1 fully consumed

        if (tid < 16) {
            float s = ((wsum[0][tid] + wsum[1][tid]) + (wsum[2][tid] + wsum[3][tid])) +
                      ((wsum[4][tid] + wsum[5][tid]) + (wsum[6][tid] + wsum[7][tid]));
            g_contrib[f * BB + rbase + tid] = s + b3f;
        }
        // next iter's (A) barrier protects wsum rewrite
    }
}

__global__ void finalize_kernel(const float* __restrict__ bias,
                                float* __restrict__ out) {
    int b = blockIdx.x * blockDim.x + threadIdx.x;
    if (b >= BB) return;
    float l = bias[0];
    #pragma unroll 16
    for (int f = 0; f < FF; ++f) l += g_contrib[f * BB + b];
    float p = 1.0f / (1.0f + expf(-l));
    out[2 * b + 0] = 1.0f - p;
    out[2 * b + 1] = p;
}

extern "C" void kernel_launch(void* const* d_in, const int* in_sizes, int n_in,
                              void* d_out, int out_size) {
    const float* x    = (const float*)d_in[0];
    const float* w1   = (const float*)d_in[1];
    const float* b1   = (const float*)d_in[2];
    const float* w2   = (const float*)d_in[3];
    const float* b2   = (const float*)d_in[4];
    const float* w3   = (const float*)d_in[5];
    const float* b3   = (const float*)d_in[6];
    const float* bias = (const float*)d_in[7];
    float* out = (float*)d_out;

    prep_kernel<<<(FF * 2048) / 256, 256>>>(w2);
    dim3 grid(NCHUNK, FF);   // 32 x 128 = 4096 CTAs
    mlp_mma_kernel<<<grid, THREADS>>>(x, w1, b1, b2, w3, b3);
    finalize_kernel<<<BB / 256, 256>>>(bias, out);
}